// round 3
// baseline (speedup 1.0000x reference)
#include <cuda_runtime.h>
#include <cuda_fp16.h>

#define D 64
#define ALPHA 0.2f
#define MAX_N 131072
#define CAP 64           // ELL row capacity; deg ~ Poisson(17), P(>63) ~ 1e-18

// Static scratch. g_cnt starts zero (BSS) and k_aggregate re-zeroes it each
// run, so graph replays always see a clean histogram.
__device__ int     g_cnt[MAX_N];
__device__ float2  g_s1[MAX_N];          // per-node source-side scores (h0,h1)
__device__ float2  g_s2[MAX_N];          // per-node dest-side scores (h0,h1)
__device__ __half2 g_xh[MAX_N * 32];     // fp16 copy of x, 2 feats per lane
__device__ float4  g_ell[MAX_N * CAP];   // per-edge record: (w0, w1, col_bits, 0)

// One warp per node: per-head scores + fp16 conversion of x (x read once).
__global__ void k_precompute(const float* __restrict__ x,
                             const float* __restrict__ W,
                             const float* __restrict__ a, int n) {
    int warp = (blockIdx.x * blockDim.x + threadIdx.x) >> 5;
    int lane = threadIdx.x & 31;
    if (warp >= n) return;
    float2 xv = reinterpret_cast<const float2*>(x)[warp * 32 + lane];
    g_xh[warp * 32 + lane] = __floats2half2_rn(xv.x, xv.y);
    int l2 = lane * 2;
    float h00 = xv.x * W[l2],      h01 = xv.y * W[l2 + 1];
    float h10 = xv.x * W[64 + l2], h11 = xv.y * W[64 + l2 + 1];
    float s10 = h00 * a[l2]       + h01 * a[l2 + 1];
    float s20 = h00 * a[64 + l2]  + h01 * a[64 + l2 + 1];
    float s11 = h10 * a[128 + l2] + h11 * a[128 + l2 + 1];
    float s21 = h10 * a[192 + l2] + h11 * a[192 + l2 + 1];
    #pragma unroll
    for (int o = 16; o; o >>= 1) {
        s10 += __shfl_xor_sync(0xffffffffu, s10, o);
        s20 += __shfl_xor_sync(0xffffffffu, s20, o);
        s11 += __shfl_xor_sync(0xffffffffu, s11, o);
        s21 += __shfl_xor_sync(0xffffffffu, s21, o);
    }
    if (lane == 0) {
        g_s1[warp] = make_float2(s10, s11);
        g_s2[warp] = make_float2(s20, s21);
    }
}

// Single edge-parallel pass: histogram slot + edge weight + ELL record write.
// One 16B record per edge -> one 32B sector of scattered write traffic.
__global__ void k_build(const int* __restrict__ row,
                        const int* __restrict__ col, int E) {
    int i = blockIdx.x * blockDim.x + threadIdx.x;
    if (i >= E) return;
    int r = row[i], c = col[i];
    int slot = atomicAdd(&g_cnt[r], 1);
    if (slot < CAP) {
        float2 s1 = g_s1[r];
        float2 s2 = g_s2[c];
        float sc0 = s1.x + s2.x;
        float sc1 = s1.y + s2.y;
        float w0 = __expf(sc0 > 0.f ? sc0 : ALPHA * sc0);
        float w1 = __expf(sc1 > 0.f ? sc1 : ALPHA * sc1);
        g_ell[(r << 6) + slot] = make_float4(w0, w1, __int_as_float(c), 0.f);
    }
}

// One warp per node: broadcast-load the 16B edge record (row-contiguous,
// L1-resident; address independent of the gather so unroll-4 gives MLP~4),
// gather the fp16 x row, register-accumulate both heads, normalize, mean.
// Also resets g_cnt for the next graph replay.
__global__ void k_aggregate(float* __restrict__ out, int n) {
    int warp = (blockIdx.x * blockDim.x + threadIdx.x) >> 5;
    int lane = threadIdx.x & 31;
    if (warp >= n) return;
    int deg = g_cnt[warp];
    if (lane == 0) g_cnt[warp] = 0;
    deg = min(deg, CAP);
    const float4* __restrict__ erow = g_ell + (warp << 6);
    float a00 = 0.f, a01 = 0.f, a10 = 0.f, a11 = 0.f;
    float rs0 = 0.f, rs1 = 0.f;
    #pragma unroll 4
    for (int j = 0; j < deg; j++) {
        float4 e = erow[j];
        int c = __float_as_int(e.z);
        float2 xf = __half22float2(g_xh[c * 32 + lane]);
        a00 += e.x * xf.x; a01 += e.x * xf.y;
        a10 += e.y * xf.x; a11 += e.y * xf.y;
        rs0 += e.x; rs1 += e.y;
    }
    float i0 = 0.5f / rs0, i1 = 0.5f / rs1;
    float2 o;
    o.x = a00 * i0 + a10 * i1;
    o.y = a01 * i0 + a11 * i1;
    reinterpret_cast<float2*>(out)[warp * 32 + lane] = o;
}

extern "C" void kernel_launch(void* const* d_in, const int* in_sizes, int n_in,
                              void* d_out, int out_size) {
    const float* x  = (const float*)d_in[0];
    const int*   ei = (const int*)d_in[1];
    const float* W  = (const float*)d_in[2];
    const float* a  = (const float*)d_in[3];
    float* out = (float*)d_out;

    int n = in_sizes[0] / D;
    int E = in_sizes[1] / 2;
    const int* row = ei;
    const int* col = ei + E;

    const int T = 256;
    int nbE = (E + T - 1) / T;
    int nbW = (n * 32 + T - 1) / T;   // one warp per node

    k_precompute<<<nbW, T>>>(x, W, a, n);
    k_build<<<nbE, T>>>(row, col, E);
    k_aggregate<<<nbW, T>>>(out, n);
}

// round 4
// speedup vs baseline: 2.1187x; 2.1187x over previous
#include <cuda_runtime.h>
#include <cuda_fp16.h>

#define D 64
#define ALPHA 0.2f
#define MAX_N 131072
#define MAX_E 2200000

// Static scratch (BSS zero-init; scan3 re-zeroes g_cnt each run so graph
// replays always see a clean histogram).
__device__ int     g_cnt[MAX_N];
__device__ int     g_rowptr[MAX_N + 1];
__device__ int     g_blocksum[512];
__device__ int     g_slot[MAX_E];        // per-edge within-row slot from hist
__device__ float4  g_rec[MAX_E];         // CSR-packed per-edge: (w0, w1, col, -)
__device__ float2  g_s1[MAX_N];          // per-node source-side scores (h0,h1)
__device__ float2  g_s2[MAX_N];          // per-node dest-side scores (h0,h1)
__device__ __half2 g_xh[MAX_N * 32];     // fp16 copy of x, 2 feats per lane

// Histogram + slot assignment (needs g_cnt == 0; restored by k_scan3).
__global__ void k_hist(const int* __restrict__ row, int E) {
    int i = blockIdx.x * blockDim.x + threadIdx.x;
    if (i < E) g_slot[i] = atomicAdd(&g_cnt[row[i]], 1);
}

// One warp per node. W/a staged as fused per-feature vectors in shared
// memory (kills the 8 strided scalar global loads -> ~16 L1 wavefronts/warp
// that made this kernel 34us).
__global__ void k_precompute(const float* __restrict__ x,
                             const float* __restrict__ W,
                             const float* __restrict__ a, int n) {
    __shared__ float v00[64], v01[64], v10[64], v11[64]; // W[h][j]*a[h][...j]
    int t = threadIdx.x;
    if (t < 64) {
        float w0 = W[t], w1 = W[64 + t];
        v00[t] = w0 * a[t];
        v01[t] = w0 * a[64 + t];
        v10[t] = w1 * a[128 + t];
        v11[t] = w1 * a[192 + t];
    }
    __syncthreads();
    int warp = (blockIdx.x * blockDim.x + t) >> 5;
    int lane = t & 31;
    if (warp >= n) return;
    float2 xv = reinterpret_cast<const float2*>(x)[warp * 32 + lane];
    g_xh[warp * 32 + lane] = __floats2half2_rn(xv.x, xv.y);
    int l2 = lane * 2;
    float s10 = xv.x * v00[l2] + xv.y * v00[l2 + 1];
    float s20 = xv.x * v01[l2] + xv.y * v01[l2 + 1];
    float s11 = xv.x * v10[l2] + xv.y * v10[l2 + 1];
    float s21 = xv.x * v11[l2] + xv.y * v11[l2 + 1];
    #pragma unroll
    for (int o = 16; o; o >>= 1) {
        s10 += __shfl_xor_sync(0xffffffffu, s10, o);
        s20 += __shfl_xor_sync(0xffffffffu, s20, o);
        s11 += __shfl_xor_sync(0xffffffffu, s11, o);
        s21 += __shfl_xor_sync(0xffffffffu, s21, o);
    }
    if (lane == 0) {
        g_s1[warp] = make_float2(s10, s11);
        g_s2[warp] = make_float2(s20, s21);
    }
}

// 3-kernel exclusive scan of g_cnt -> g_rowptr
__global__ void k_scan1(int n) {
    __shared__ int sh[512];
    int t = threadIdx.x;
    int i = blockIdx.x * 512 + t;
    int v = (i < n) ? g_cnt[i] : 0;
    sh[t] = v;
    __syncthreads();
    #pragma unroll
    for (int o = 1; o < 512; o <<= 1) {
        int tmp = (t >= o) ? sh[t - o] : 0;
        __syncthreads();
        sh[t] += tmp;
        __syncthreads();
    }
    if (i < n) g_rowptr[i] = sh[t] - v;
    if (t == 511) g_blocksum[blockIdx.x] = sh[511];
}

__global__ void k_scan2(int nb) {
    __shared__ int sh[512];
    int t = threadIdx.x;
    int v = (t < nb) ? g_blocksum[t] : 0;
    sh[t] = v;
    __syncthreads();
    #pragma unroll
    for (int o = 1; o < 512; o <<= 1) {
        int tmp = (t >= o) ? sh[t - o] : 0;
        __syncthreads();
        sh[t] += tmp;
        __syncthreads();
    }
    if (t < nb) g_blocksum[t] = sh[t] - v;
}

// Adds block bases; re-zeroes g_cnt for the next graph replay.
__global__ void k_scan3(int n, int E) {
    int i = blockIdx.x * 512 + threadIdx.x;
    if (i < n) {
        g_rowptr[i] += g_blocksum[blockIdx.x];
        g_cnt[i] = 0;
    }
    if (i == n) g_rowptr[n] = E;
}

// Edge-parallel CSR fill (atomic-free): compute both head weights, write one
// packed 16B record into the compact CSR array.
__global__ void k_scatter(const int* __restrict__ row,
                          const int* __restrict__ col, int E) {
    int i = blockIdx.x * blockDim.x + threadIdx.x;
    if (i >= E) return;
    int r = row[i], c = col[i];
    int pos = g_rowptr[r] + g_slot[i];
    float2 s1 = g_s1[r];
    float2 s2 = g_s2[c];
    float sc0 = s1.x + s2.x;
    float sc1 = s1.y + s2.y;
    float w0 = __expf(sc0 > 0.f ? sc0 : ALPHA * sc0);
    float w1 = __expf(sc1 > 0.f ? sc1 : ALPHA * sc1);
    g_rec[pos] = make_float4(w0, w1, __int_as_float(c), 0.f);
}

// One warp per node (R1-style serial loop — known good): one broadcast
// LDG.128 record + one fp16 gather per edge, register accumulate, normalize.
__global__ void k_aggregate(float* __restrict__ out, int n) {
    int warp = (blockIdx.x * blockDim.x + threadIdx.x) >> 5;
    int lane = threadIdx.x & 31;
    if (warp >= n) return;
    int beg = g_rowptr[warp];
    int end = g_rowptr[warp + 1];
    float a00 = 0.f, a01 = 0.f, a10 = 0.f, a11 = 0.f;
    float rs0 = 0.f, rs1 = 0.f;
    for (int e = beg; e < end; e++) {
        float4 r = g_rec[e];
        int c = __float_as_int(r.z);
        float2 xf = __half22float2(g_xh[c * 32 + lane]);
        a00 += r.x * xf.x; a01 += r.x * xf.y;
        a10 += r.y * xf.x; a11 += r.y * xf.y;
        rs0 += r.x; rs1 += r.y;
    }
    float i0 = 0.5f / rs0, i1 = 0.5f / rs1;
    float2 o;
    o.x = a00 * i0 + a10 * i1;
    o.y = a01 * i0 + a11 * i1;
    reinterpret_cast<float2*>(out)[warp * 32 + lane] = o;
}

extern "C" void kernel_launch(void* const* d_in, const int* in_sizes, int n_in,
                              void* d_out, int out_size) {
    const float* x  = (const float*)d_in[0];
    const int*   ei = (const int*)d_in[1];
    const float* W  = (const float*)d_in[2];
    const float* a  = (const float*)d_in[3];
    float* out = (float*)d_out;

    int n = in_sizes[0] / D;
    int E = in_sizes[1] / 2;
    const int* row = ei;
    const int* col = ei + E;

    const int T = 256;
    int nbE = (E + T - 1) / T;
    int nbW = (n * 32 + T - 1) / T;   // one warp per node
    int nbS = (n + 511) / 512;

    k_hist<<<nbE, T>>>(row, E);
    k_precompute<<<nbW, T>>>(x, W, a, n);
    k_scan1<<<nbS, 512>>>(n);
    k_scan2<<<1, 512>>>(nbS);
    k_scan3<<<(n + 512) / 512, 512>>>(n, E);
    k_scatter<<<nbE, T>>>(row, col, E);
    k_aggregate<<<nbW, T>>>(out, n);
}

// round 5
// speedup vs baseline: 2.6494x; 1.2505x over previous
#include <cuda_runtime.h>
#include <cuda_fp16.h>

#define D 64
#define ALPHA 0.2f
#define MAX_N 131072
#define MAX_E 2200000
#define SCAN_B 512

// Static scratch (BSS zero-init; k_scan_apply re-zeroes g_cnt every run so
// graph replays always see a clean histogram).
__device__ int     g_cnt[MAX_N];
__device__ int     g_rowptr[MAX_N + 1];
__device__ int     g_blocksum[SCAN_B];
__device__ int     g_slot[MAX_E];     // per-edge within-row slot from hist
__device__ __align__(16) unsigned long long g_rec[MAX_E]; // (col<<32)|half2(w0,w1)
__device__ float2  g_s1[MAX_N];       // per-node source-side scores (h0,h1)
__device__ float2  g_s2[MAX_N];       // per-node dest-side scores (h0,h1)
__device__ __half2 g_xh[MAX_N * 32];  // fp16 copy of x, 2 feats per lane

// Fused: blocks [0,nbE) do the edge histogram (slot assignment); blocks
// [nbE, nbE+nbW) do per-node score precompute + fp16 conversion of x.
__global__ void k_pre_hist(const float* __restrict__ x,
                           const float* __restrict__ W,
                           const float* __restrict__ a,
                           const int* __restrict__ row,
                           int n, int E, int nbE) {
    int t = threadIdx.x;
    if ((int)blockIdx.x < nbE) {
        int i = blockIdx.x * blockDim.x + t;
        if (i < E) g_slot[i] = atomicAdd(&g_cnt[row[i]], 1);
        return;
    }
    __shared__ float v00[64], v01[64], v10[64], v11[64]; // W[h][j]*a[h][..j]
    if (t < 64) {
        float w0 = W[t], w1 = W[64 + t];
        v00[t] = w0 * a[t];
        v01[t] = w0 * a[64 + t];
        v10[t] = w1 * a[128 + t];
        v11[t] = w1 * a[192 + t];
    }
    __syncthreads();
    int b = blockIdx.x - nbE;
    int warp = (b * blockDim.x + t) >> 5;
    int lane = t & 31;
    if (warp >= n) return;
    float2 xv = reinterpret_cast<const float2*>(x)[warp * 32 + lane];
    g_xh[warp * 32 + lane] = __floats2half2_rn(xv.x, xv.y);
    int l2 = lane * 2;
    float s10 = xv.x * v00[l2] + xv.y * v00[l2 + 1];
    float s20 = xv.x * v01[l2] + xv.y * v01[l2 + 1];
    float s11 = xv.x * v10[l2] + xv.y * v10[l2 + 1];
    float s21 = xv.x * v11[l2] + xv.y * v11[l2 + 1];
    #pragma unroll
    for (int o = 16; o; o >>= 1) {
        s10 += __shfl_xor_sync(0xffffffffu, s10, o);
        s20 += __shfl_xor_sync(0xffffffffu, s20, o);
        s11 += __shfl_xor_sync(0xffffffffu, s11, o);
        s21 += __shfl_xor_sync(0xffffffffu, s21, o);
    }
    if (lane == 0) {
        g_s1[warp] = make_float2(s10, s11);
        g_s2[warp] = make_float2(s20, s21);
    }
}

// Block-local exclusive scan of g_cnt -> g_rowptr (local) + block totals.
__global__ void k_scan1(int n) {
    __shared__ int sh[SCAN_B];
    int t = threadIdx.x;
    int i = blockIdx.x * SCAN_B + t;
    int v = (i < n) ? g_cnt[i] : 0;
    sh[t] = v;
    __syncthreads();
    #pragma unroll
    for (int o = 1; o < SCAN_B; o <<= 1) {
        int tmp = (t >= o) ? sh[t - o] : 0;
        __syncthreads();
        sh[t] += tmp;
        __syncthreads();
    }
    if (i < n) g_rowptr[i] = sh[t] - v;
    if (t == SCAN_B - 1) g_blocksum[blockIdx.x] = sh[t];
}

// Every block redundantly scans the (<=512) block sums in smem, adds its own
// base to the local prefixes, re-zeroes g_cnt, and caps rowptr[n]=E.
__global__ void k_scan_apply(int n, int E, int nb) {
    __shared__ int sh[SCAN_B];
    int t = threadIdx.x;
    sh[t] = (t < nb) ? g_blocksum[t] : 0;
    __syncthreads();
    #pragma unroll
    for (int o = 1; o < SCAN_B; o <<= 1) {
        int tmp = (t >= o) ? sh[t - o] : 0;
        __syncthreads();
        sh[t] += tmp;
        __syncthreads();
    }
    int base = (blockIdx.x == 0) ? 0 : sh[blockIdx.x - 1];
    int i = blockIdx.x * SCAN_B + t;
    if (i < n) {
        g_rowptr[i] += base;
        g_cnt[i] = 0;
    }
    if (i == n) g_rowptr[n] = E;
}

// Edge-parallel CSR fill (atomic-free): both head weights in fp16, packed
// with the column index into one 8-byte record.
__global__ void k_scatter(const int* __restrict__ row,
                          const int* __restrict__ col, int E) {
    int i = blockIdx.x * blockDim.x + threadIdx.x;
    if (i >= E) return;
    int r = row[i], c = col[i];
    int pos = g_rowptr[r] + g_slot[i];
    float2 s1 = g_s1[r];
    float2 s2 = g_s2[c];
    float sc0 = s1.x + s2.x;
    float sc1 = s1.y + s2.y;
    float w0 = __expf(sc0 > 0.f ? sc0 : ALPHA * sc0);
    float w1 = __expf(sc1 > 0.f ? sc1 : ALPHA * sc1);
    __half2 wh = __floats2half2_rn(w0, w1);
    unsigned wbits = *reinterpret_cast<unsigned*>(&wh);
    g_rec[pos] = ((unsigned long long)(unsigned)c << 32) | wbits;
}

// One warp per node. Records consumed in aligned pairs (one LDG.128 covers
// two edges; the two gathers are independent -> MLP 2 on the L2-resident x).
__global__ void k_aggregate(float* __restrict__ out, int n) {
    int warp = (blockIdx.x * blockDim.x + threadIdx.x) >> 5;
    int lane = threadIdx.x & 31;
    if (warp >= n) return;
    int beg = g_rowptr[warp];
    int end = g_rowptr[warp + 1];
    float a00 = 0.f, a01 = 0.f, a10 = 0.f, a11 = 0.f;
    float rs0 = 0.f, rs1 = 0.f;

    int e = beg;
    if (e < end && (e & 1)) {          // head: align to even index
        unsigned long long r = g_rec[e];
        unsigned lo = (unsigned)r;
        int c = (int)(r >> 32);
        float2 w = __half22float2(*reinterpret_cast<__half2*>(&lo));
        float2 xf = __half22float2(g_xh[c * 32 + lane]);
        a00 += w.x * xf.x; a01 += w.x * xf.y;
        a10 += w.y * xf.x; a11 += w.y * xf.y;
        rs0 += w.x; rs1 += w.y;
        e++;
    }
    for (; e + 1 < end; e += 2) {      // aligned pair
        uint4 q = *reinterpret_cast<const uint4*>(&g_rec[e]);
        int c0 = (int)q.y, c1 = (int)q.w;
        float2 w0 = __half22float2(*reinterpret_cast<__half2*>(&q.x));
        float2 w1 = __half22float2(*reinterpret_cast<__half2*>(&q.z));
        float2 x0 = __half22float2(g_xh[c0 * 32 + lane]);
        float2 x1 = __half22float2(g_xh[c1 * 32 + lane]);
        a00 += w0.x * x0.x; a01 += w0.x * x0.y;
        a10 += w0.y * x0.x; a11 += w0.y * x0.y;
        rs0 += w0.x; rs1 += w0.y;
        a00 += w1.x * x1.x; a01 += w1.x * x1.y;
        a10 += w1.y * x1.x; a11 += w1.y * x1.y;
        rs0 += w1.x; rs1 += w1.y;
    }
    if (e < end) {                     // tail
        unsigned long long r = g_rec[e];
        unsigned lo = (unsigned)r;
        int c = (int)(r >> 32);
        float2 w = __half22float2(*reinterpret_cast<__half2*>(&lo));
        float2 xf = __half22float2(g_xh[c * 32 + lane]);
        a00 += w.x * xf.x; a01 += w.x * xf.y;
        a10 += w.y * xf.x; a11 += w.y * xf.y;
        rs0 += w.x; rs1 += w.y;
    }

    float i0 = 0.5f / rs0, i1 = 0.5f / rs1;
    float2 o;
    o.x = a00 * i0 + a10 * i1;
    o.y = a01 * i0 + a11 * i1;
    reinterpret_cast<float2*>(out)[warp * 32 + lane] = o;
}

extern "C" void kernel_launch(void* const* d_in, const int* in_sizes, int n_in,
                              void* d_out, int out_size) {
    const float* x  = (const float*)d_in[0];
    const int*   ei = (const int*)d_in[1];
    const float* W  = (const float*)d_in[2];
    const float* a  = (const float*)d_in[3];
    float* out = (float*)d_out;

    int n = in_sizes[0] / D;
    int E = in_sizes[1] / 2;
    const int* row = ei;
    const int* col = ei + E;

    const int T = 256;
    int nbE = (E + T - 1) / T;
    int nbW = (n * 32 + T - 1) / T;          // one warp per node
    int nbS = (n + SCAN_B - 1) / SCAN_B;     // must be <= SCAN_B

    k_pre_hist<<<nbE + nbW, T>>>(x, W, a, row, n, E, nbE);
    k_scan1<<<nbS, SCAN_B>>>(n);
    k_scan_apply<<<(n + SCAN_B) / SCAN_B, SCAN_B>>>(n, E, nbS);
    k_scatter<<<nbE, T>>>(row, col, E);
    k_aggregate<<<nbW, T>>>(out, n);
}